// round 1
// baseline (speedup 1.0000x reference)
#include <cuda_runtime.h>
#include <math.h>

#define BATCH 16
#define TLEN 800
#define DDIM 512
#define VOC 4000
#define LMAX 100
#define SEXT 201            // 2*LMAX + 1
#define NEMIT 101           // blank + LMAX labels
#define NEGV (-1e30f)

// ---------------- device scratch (no allocs allowed) ----------------
__device__ float g_logits[(size_t)BATCH * TLEN * VOC];   // 204.8 MB
__device__ float g_lse[BATCH * TLEN];
__device__ float g_emit[BATCH * TLEN * NEMIT];           // 5.2 MB
__device__ float g_loss[BATCH];

// ---------------- kernel 1: projection GEMM --------------------------
// C[r, v] = sum_d hs[r, d] * W[d, v] + bias[v];  r = b*TLEN + t
// 128x128 tile, TK=8, 256 threads, 8x8 per-thread micro-tile.
__global__ __launch_bounds__(256) void gemm_kernel(const float* __restrict__ A,
                                                   const float* __restrict__ Wm,
                                                   const float* __restrict__ bias) {
    __shared__ __align__(16) float As[8][128];
    __shared__ __align__(16) float Bs[8][128];

    const int tid = threadIdx.x;
    const int m0 = blockIdx.y * 128;
    const int n0 = blockIdx.x * 128;
    const int tx = tid & 15;
    const int ty = tid >> 4;

    float acc[8][8];
#pragma unroll
    for (int i = 0; i < 8; i++)
#pragma unroll
        for (int j = 0; j < 8; j++) acc[i][j] = 0.f;

    // A tile load mapping: one float4 per thread
    const int arow = tid >> 1;
    const int akk  = (tid & 1) << 2;
    // B tile load mapping: one float4 per thread
    const int bkk  = tid >> 5;
    const int bcol = (tid & 31) << 2;

    const float* Ap = A + (size_t)(m0 + arow) * DDIM + akk;
    const int gn = n0 + bcol;
    const bool bok = gn < VOC;   // VOC % 4 == 0 -> whole float4 in or out

    for (int k0 = 0; k0 < DDIM; k0 += 8) {
        float4 av = *(const float4*)(Ap + k0);
        As[akk + 0][arow] = av.x;
        As[akk + 1][arow] = av.y;
        As[akk + 2][arow] = av.z;
        As[akk + 3][arow] = av.w;

        float4 bv = make_float4(0.f, 0.f, 0.f, 0.f);
        if (bok) bv = *(const float4*)(Wm + (size_t)(k0 + bkk) * VOC + gn);
        *(float4*)&Bs[bkk][bcol] = bv;

        __syncthreads();
#pragma unroll
        for (int kk = 0; kk < 8; kk++) {
            float4 a0 = *(const float4*)&As[kk][ty * 4];
            float4 a1 = *(const float4*)&As[kk][64 + ty * 4];
            float4 b0 = *(const float4*)&Bs[kk][tx * 4];
            float4 b1 = *(const float4*)&Bs[kk][64 + tx * 4];
            float ar[8] = {a0.x, a0.y, a0.z, a0.w, a1.x, a1.y, a1.z, a1.w};
            float br[8] = {b0.x, b0.y, b0.z, b0.w, b1.x, b1.y, b1.z, b1.w};
#pragma unroll
            for (int i = 0; i < 8; i++)
#pragma unroll
                for (int j = 0; j < 8; j++)
                    acc[i][j] = fmaf(ar[i], br[j], acc[i][j]);
        }
        __syncthreads();
    }

    // epilogue: add bias, write logits (guard the last partial N tile)
#pragma unroll
    for (int i = 0; i < 8; i++) {
        int gm = m0 + ((i < 4) ? (ty * 4 + i) : (64 + ty * 4 + i - 4));
#pragma unroll
        for (int jh = 0; jh < 2; jh++) {
            int gc = n0 + ((jh == 0) ? tx * 4 : 64 + tx * 4);
            if (gc < VOC) {
                int jb = jh * 4;
                float4 o;
                o.x = acc[i][jb + 0] + bias[gc + 0];
                o.y = acc[i][jb + 1] + bias[gc + 1];
                o.z = acc[i][jb + 2] + bias[gc + 2];
                o.w = acc[i][jb + 3] + bias[gc + 3];
                *(float4*)&g_logits[(size_t)gm * VOC + gc] = o;
            }
        }
    }
}

// ---------------- kernel 2: per-row log-sum-exp -----------------------
__global__ __launch_bounds__(256) void lse_kernel() {
    const int row = blockIdx.x;
    const float* p = g_logits + (size_t)row * VOC;
    const int tid = threadIdx.x;

    float v[16];
    float mx = -3.4e38f;
#pragma unroll
    for (int i = 0; i < 16; i++) {
        int idx = tid + i * 256;
        v[i] = (idx < VOC) ? p[idx] : -3.4e38f;
        mx = fmaxf(mx, v[i]);
    }

    __shared__ float red[256];
    red[tid] = mx;
    __syncthreads();
    for (int st = 128; st > 0; st >>= 1) {
        if (tid < st) red[tid] = fmaxf(red[tid], red[tid + st]);
        __syncthreads();
    }
    mx = red[0];
    __syncthreads();

    float s = 0.f;
#pragma unroll
    for (int i = 0; i < 16; i++) {
        int idx = tid + i * 256;
        if (idx < VOC) s += expf(v[i] - mx);
    }
    red[tid] = s;
    __syncthreads();
    for (int st = 128; st > 0; st >>= 1) {
        if (tid < st) red[tid] += red[tid + st];
        __syncthreads();
    }
    if (tid == 0) g_lse[row] = mx + logf(red[0]);
}

// ---------------- kernel 3: gather emit table -------------------------
// emit[b][t][j]: j=0 -> blank(0); j=1..LMAX -> ys_pad[b][j-1]
__global__ __launch_bounds__(128) void gather_kernel(const int* __restrict__ ys_pad) {
    const int bt = blockIdx.x;
    const int j = threadIdx.x;
    if (j >= NEMIT) return;
    const int b = bt / TLEN;
    const int label = (j == 0) ? 0 : ys_pad[b * LMAX + (j - 1)];
    g_emit[(size_t)bt * NEMIT + j] =
        g_logits[(size_t)bt * VOC + label] - g_lse[bt];
}

// ---------------- kernel 4: CTC forward recursion ----------------------
__global__ __launch_bounds__(256) void ctc_kernel(const int* __restrict__ hlens,
                                                  const int* __restrict__ ys_pad,
                                                  const int* __restrict__ ys_lens) {
    const int b = blockIdx.x;
    const int s = threadIdx.x;
    __shared__ float al[SEXT + 2];   // al[s+2] = alpha[s]; al[0],al[1] = NEG guards

    const float* eb = g_emit + (size_t)b * TLEN * NEMIT;
    const bool act = s < SEXT;
    const int j = (s & 1) ? ((s >> 1) + 1) : 0;   // emit-table column

    bool skip = false;
    if (act && (s & 1) && s >= 3) {
        int cur  = ys_pad[b * LMAX + (s >> 1)];
        int prev = ys_pad[b * LMAX + (s >> 1) - 1];
        skip = (cur != prev);
    }

    if (s < 2) al[s] = NEGV;
    if (act) al[s + 2] = (s < 2) ? eb[j] : NEGV;   // alpha0 = emit[t=0] at s=0,1

    const int hl = hlens[b];
    float e1 = NEGV;
    if (act && hl > 1) e1 = eb[NEMIT + j];         // prefetch t=1
    __syncthreads();

    for (int t = 1; t < hl; t++) {
        float e = e1;
        if (act && t + 1 < hl) e1 = eb[(size_t)(t + 1) * NEMIT + j];  // prefetch next

        float a0 = act ? al[s + 2] : NEGV;
        float a1 = act ? al[s + 1] : NEGV;
        float a2 = (act && skip) ? al[s] : NEGV;
        __syncthreads();
        if (act) {
            float m = fmaxf(a0, fmaxf(a1, a2));
            float sum = expf(a0 - m) + expf(a1 - m) + expf(a2 - m);
            al[s + 2] = m + logf(sum) + e;
        }
        __syncthreads();
    }

    if (s == 0) {
        int L = ys_lens[b];
        int idx = 2 * L;
        float aL = al[idx + 2];
        float aP = al[idx + 1];
        float m = fmaxf(aL, aP);
        float loss = -(m + logf(expf(aL - m) + expf(aP - m)));
        if (!isfinite(loss) || loss >= 1e29f) loss = 0.f;  // zero_infinity
        g_loss[b] = loss;
    }
}

// ---------------- kernel 5: deterministic final reduce -----------------
__global__ void finalize_kernel(float* __restrict__ out) {
    float sum = 0.f;
    for (int i = 0; i < BATCH; i++) sum += g_loss[i];
    out[0] = sum / (float)BATCH;
}

// ---------------- launch --------------------------------------------------
extern "C" void kernel_launch(void* const* d_in, const int* in_sizes, int n_in,
                              void* d_out, int out_size) {
    const float* hs     = (const float*)d_in[0];  // [B, T, D]
    const float* Wm     = (const float*)d_in[1];  // [D, V]
    const float* bias   = (const float*)d_in[2];  // [V]
    const int* hlens    = (const int*)d_in[3];    // [B]
    const int* ys_pad   = (const int*)d_in[4];    // [B, LMAX]
    const int* ys_lens  = (const int*)d_in[5];    // [B]
    float* out = (float*)d_out;

    dim3 gemm_grid((VOC + 127) / 128, (BATCH * TLEN) / 128);  // (32, 100)
    gemm_kernel<<<gemm_grid, 256>>>(hs, Wm, bias);
    lse_kernel<<<BATCH * TLEN, 256>>>();
    gather_kernel<<<BATCH * TLEN, 128>>>(ys_pad);
    ctc_kernel<<<BATCH, 256>>>(hlens, ys_pad, ys_lens);
    finalize_kernel<<<1, 1>>>(out);
}

// round 2
// speedup vs baseline: 1.1080x; 1.1080x over previous
#include <cuda_runtime.h>
#include <math.h>

#define BATCH 16
#define TLEN 800
#define DDIM 512
#define VOC 4000
#define LMAX 100
#define SEXT 201            // 2*LMAX + 1
#define NEMIT 101           // blank + LMAX labels
#define NROWS (BATCH * TLEN)
#define NTILES 32           // ceil(VOC/128)
#define GSTRIDE 104         // padded gather stride
#define NEGV (-1e30f)

// ---------------- device scratch (no allocs allowed) ----------------
__device__ float g_pmax[NROWS * NTILES];
__device__ float g_psum[NROWS * NTILES];
__device__ float g_gath[(size_t)NROWS * GSTRIDE];   // gathered label logits
__device__ float g_lse[NROWS];
__device__ float g_emit[(size_t)NROWS * NEMIT];
__device__ int   g_slot[BATCH * VOC];               // col -> emit slot (-1 absent)
__device__ float g_loss[BATCH];

// ---------------- kernel 0a: init slot map ---------------------------
__global__ void init_slot_kernel() {
    int i = blockIdx.x * blockDim.x + threadIdx.x;
    if (i < BATCH * VOC) g_slot[i] = -1;
}

// ---------------- kernel 0b: write label slots ------------------------
__global__ void write_slot_kernel(const int* __restrict__ ys_pad) {
    int b = blockIdx.x;
    int j = threadIdx.x;
    if (j < LMAX) {
        int col = ys_pad[b * LMAX + j];
        g_slot[b * VOC + col] = j + 1;     // emit index 1..LMAX
    }
    if (j == LMAX) g_slot[b * VOC + 0] = 0; // blank
}

// ---------------- kernel 1: GEMM + fused LSE partials + label gather --
// C[r, v] = sum_d hs[r, d] * W[d, v] + bias[v];  r = b*TLEN + t
// 128x128 tile, TK=8, 256 threads, 8x8 per-thread micro-tile.
__global__ __launch_bounds__(256, 2) void gemm_kernel(const float* __restrict__ A,
                                                      const float* __restrict__ Wm,
                                                      const float* __restrict__ bias) {
    __shared__ __align__(16) float As[8][128];
    __shared__ __align__(16) float Bs[8][128];
    __shared__ float red[128][17];      // padded to kill bank conflicts
    __shared__ float rowmax_s[128];
    __shared__ int sslot[2][128];

    const int tid = threadIdx.x;
    const int m0 = blockIdx.y * 128;
    const int n0 = blockIdx.x * 128;
    const int tx = tid & 15;
    const int ty = tid >> 4;

    // per-block batch span (rows m0..m0+127 cross at most one batch boundary)
    const int rb0 = m0 / TLEN;
    const int rb1 = (m0 + 127) / TLEN;

    // preload slot slices for both possible batches (overlaps mainloop)
    if (tid < 128) {
        int gc = n0 + tid;
        sslot[0][tid] = (gc < VOC) ? g_slot[rb0 * VOC + gc] : -1;
        sslot[1][tid] = (gc < VOC) ? g_slot[rb1 * VOC + gc] : -1;
    }

    float acc[8][8];
#pragma unroll
    for (int i = 0; i < 8; i++)
#pragma unroll
        for (int j = 0; j < 8; j++) acc[i][j] = 0.f;

    const int arow = tid >> 1;
    const int akk  = (tid & 1) << 2;
    const int bkk  = tid >> 5;
    const int bcol = (tid & 31) << 2;

    const float* Ap = A + (size_t)(m0 + arow) * DDIM + akk;
    const int gn = n0 + bcol;
    const bool bok = gn < VOC;

    float4 av = *(const float4*)(Ap);
    float4 bv = make_float4(0.f, 0.f, 0.f, 0.f);
    if (bok) bv = *(const float4*)(Wm + (size_t)bkk * VOC + gn);

    for (int k0 = 0; k0 < DDIM; k0 += 8) {
        As[akk + 0][arow] = av.x;
        As[akk + 1][arow] = av.y;
        As[akk + 2][arow] = av.z;
        As[akk + 3][arow] = av.w;
        *(float4*)&Bs[bkk][bcol] = bv;
        __syncthreads();

        if (k0 + 8 < DDIM) {
            av = *(const float4*)(Ap + k0 + 8);
            if (bok) bv = *(const float4*)(Wm + (size_t)(k0 + 8 + bkk) * VOC + gn);
        }

#pragma unroll
        for (int kk = 0; kk < 8; kk++) {
            float4 a0 = *(const float4*)&As[kk][ty * 4];
            float4 a1 = *(const float4*)&As[kk][64 + ty * 4];
            float4 b0 = *(const float4*)&Bs[kk][tx * 4];
            float4 b1 = *(const float4*)&Bs[kk][64 + tx * 4];
            float ar[8] = {a0.x, a0.y, a0.z, a0.w, a1.x, a1.y, a1.z, a1.w};
            float br[8] = {b0.x, b0.y, b0.z, b0.w, b1.x, b1.y, b1.z, b1.w};
#pragma unroll
            for (int i = 0; i < 8; i++)
#pragma unroll
                for (int j = 0; j < 8; j++)
                    acc[i][j] = fmaf(ar[i], br[j], acc[i][j]);
        }
        __syncthreads();
    }

    // ---- epilogue: bias add, LSE partials, label gather ----
    // column/row index helpers
    int lcol[8], grow[8];
#pragma unroll
    for (int j = 0; j < 8; j++) lcol[j] = (j < 4) ? (tx * 4 + j) : (64 + tx * 4 + (j - 4));
#pragma unroll
    for (int i = 0; i < 8; i++) {
        int ri = (i < 4) ? (ty * 4 + i) : (64 + ty * 4 + (i - 4));
        grow[i] = ri;  // row within tile
    }

    float bias_c[8];
#pragma unroll
    for (int j = 0; j < 8; j++) {
        int gc = n0 + lcol[j];
        bias_c[j] = (gc < VOC) ? bias[gc] : 0.f;
    }
#pragma unroll
    for (int i = 0; i < 8; i++)
#pragma unroll
        for (int j = 0; j < 8; j++) acc[i][j] += bias_c[j];

    // pass 1: row max over this block's columns
#pragma unroll
    for (int i = 0; i < 8; i++) {
        float m = -3.4e38f;
#pragma unroll
        for (int j = 0; j < 8; j++)
            if (n0 + lcol[j] < VOC) m = fmaxf(m, acc[i][j]);
        red[grow[i]][tx] = m;
    }
    __syncthreads();
    if (tid < 128) {
        float m = red[tid][0];
#pragma unroll
        for (int k = 1; k < 16; k++) m = fmaxf(m, red[tid][k]);
        rowmax_s[tid] = m;
    }
    __syncthreads();

    // pass 2: sum exp(x - rowmax)
#pragma unroll
    for (int i = 0; i < 8; i++) {
        float mrow = rowmax_s[grow[i]];
        float s = 0.f;
#pragma unroll
        for (int j = 0; j < 8; j++)
            if (n0 + lcol[j] < VOC) s += __expf(acc[i][j] - mrow);
        red[grow[i]][tx] = s;
    }
    __syncthreads();
    if (tid < 128) {
        float s = red[tid][0];
#pragma unroll
        for (int k = 1; k < 16; k++) s += red[tid][k];
        int gr = m0 + tid;
        g_pmax[gr * NTILES + blockIdx.x] = rowmax_s[tid];
        g_psum[gr * NTILES + blockIdx.x] = s;
    }

    // label gather: scatter logits at label columns
#pragma unroll
    for (int i = 0; i < 8; i++) {
        int gr = m0 + grow[i];
        int bb = (rb1 > rb0 && gr >= rb1 * TLEN) ? 1 : 0;
#pragma unroll
        for (int j = 0; j < 8; j++) {
            if (n0 + lcol[j] < VOC) {
                int slot = sslot[bb][lcol[j]];
                if (slot >= 0) g_gath[(size_t)gr * GSTRIDE + slot] = acc[i][j];
            }
        }
    }
}

// ---------------- kernel 2: combine LSE partials ----------------------
__global__ __launch_bounds__(32) void lse_reduce_kernel() {
    const int row = blockIdx.x;
    const int lane = threadIdx.x;
    float pm = g_pmax[row * NTILES + lane];
    float ps = g_psum[row * NTILES + lane];
    float M = pm;
#pragma unroll
    for (int o = 16; o; o >>= 1) M = fmaxf(M, __shfl_xor_sync(~0u, M, o));
    float v = ps * __expf(pm - M);
#pragma unroll
    for (int o = 16; o; o >>= 1) v += __shfl_xor_sync(~0u, v, o);
    if (lane == 0) g_lse[row] = M + __logf(v);
}

// ---------------- kernel 3: expand gathered logits to emit table -------
__global__ __launch_bounds__(128) void expand_kernel(const int* __restrict__ ys_pad) {
    const int row = blockIdx.x;
    const int j = threadIdx.x;
    if (j >= NEMIT) return;
    const int b = row / TLEN;
    const int col = (j == 0) ? 0 : ys_pad[b * LMAX + (j - 1)];
    const int slot = g_slot[b * VOC + col];
    g_emit[(size_t)row * NEMIT + j] = g_gath[(size_t)row * GSTRIDE + slot] - g_lse[row];
}

// ---------------- kernel 4: CTC forward recursion (double-buffered) ----
__global__ __launch_bounds__(224) void ctc_kernel(const int* __restrict__ hlens,
                                                  const int* __restrict__ ys_pad,
                                                  const int* __restrict__ ys_lens) {
    const int b = blockIdx.x;
    const int s = threadIdx.x;
    __shared__ float al[2][SEXT + 2];   // al[p][s+2] = alpha[s]

    const float* eb = g_emit + (size_t)b * TLEN * NEMIT;
    const bool act = s < SEXT;
    const int j = (s & 1) ? ((s >> 1) + 1) : 0;

    bool skip = false;
    if (act && (s & 1) && s >= 3) {
        int cur  = ys_pad[b * LMAX + (s >> 1)];
        int prev = ys_pad[b * LMAX + (s >> 1) - 1];
        skip = (cur != prev);
    }

    if (s < 2) { al[0][s] = NEGV; al[1][s] = NEGV; }
    if (act) al[0][s + 2] = (s < 2) ? eb[j] : NEGV;

    const int hl = hlens[b];
    float e1 = NEGV;
    if (act && hl > 1) e1 = eb[NEMIT + j];
    __syncthreads();

    int p = 0;
    for (int t = 1; t < hl; t++) {
        float e = e1;
        if (act && t + 1 < hl) e1 = eb[(size_t)(t + 1) * NEMIT + j];

        if (act) {
            float a0 = al[p][s + 2];
            float a1 = al[p][s + 1];
            float a2 = skip ? al[p][s] : NEGV;
            float m = fmaxf(a0, fmaxf(a1, a2));
            float w = __expf(a0 - m) + __expf(a1 - m) + __expf(a2 - m);
            al[1 - p][s + 2] = m + __logf(w) + e;
        }
        __syncthreads();
        p ^= 1;
    }

    if (s == 0) {
        int L = ys_lens[b];
        int idx = 2 * L;
        float aL = al[p][idx + 2];
        float aP = al[p][idx + 1];
        float m = fmaxf(aL, aP);
        float loss = -(m + __logf(__expf(aL - m) + __expf(aP - m)));
        if (!isfinite(loss) || loss >= 1e29f) loss = 0.f;
        g_loss[b] = loss;
    }
}

// ---------------- kernel 5: deterministic final reduce -----------------
__global__ void finalize_kernel(float* __restrict__ out) {
    float sum = 0.f;
    for (int i = 0; i < BATCH; i++) sum += g_loss[i];
    out[0] = sum / (float)BATCH;
}

// ---------------- launch --------------------------------------------------
extern "C" void kernel_launch(void* const* d_in, const int* in_sizes, int n_in,
                              void* d_out, int out_size) {
    const float* hs     = (const float*)d_in[0];  // [B, T, D]
    const float* Wm     = (const float*)d_in[1];  // [D, V]
    const float* bias   = (const float*)d_in[2];  // [V]
    const int* hlens    = (const int*)d_in[3];    // [B]
    const int* ys_pad   = (const int*)d_in[4];    // [B, LMAX]
    const int* ys_lens  = (const int*)d_in[5];    // [B]
    float* out = (float*)d_out;

    init_slot_kernel<<<(BATCH * VOC + 255) / 256, 256>>>();
    write_slot_kernel<<<BATCH, 128>>>(ys_pad);

    dim3 gemm_grid(NTILES, NROWS / 128);  // (32, 100)
    gemm_kernel<<<gemm_grid, 256>>>(hs, Wm, bias);

    lse_reduce_kernel<<<NROWS, 32>>>();
    expand_kernel<<<NROWS, 128>>>(ys_pad);
    ctc_kernel<<<BATCH, 224>>>(hlens, ys_pad, ys_lens);
    finalize_kernel<<<1, 1>>>(out);
}

// round 4
// speedup vs baseline: 2.6765x; 2.4156x over previous
#include <cuda_runtime.h>
#include <cuda_bf16.h>
#include <math.h>
#include <stdint.h>

#define BATCH 16
#define TLEN 800
#define DDIM 512
#define VOC 4000
#define VPAD 4096
#define LMAX 100
#define SEXT 201
#define NEMIT 101
#define NROWS (BATCH * TLEN)
#define NTILES 32
#define GSTRIDE 104
#define NEGV (-1e30f)

#define RSTB 80          // smem row stride in bytes (40 bf16)
#define TILE_BYTES 10240 // 128 rows * 80 B

// ---------------- device scratch ----------------
__device__ __align__(16) __nv_bfloat16 g_Abf[(size_t)NROWS * DDIM];   // 13.1MB
__device__ __align__(16) __nv_bfloat16 g_Wt[(size_t)VPAD * DDIM];     // 4.2MB [v][k]
__device__ float g_pmax[NROWS * NTILES];
__device__ float g_psum[NROWS * NTILES];
__device__ float g_gath[(size_t)NROWS * GSTRIDE];
__device__ float g_emit[(size_t)NROWS * NEMIT];
__device__ int   g_slot[BATCH * VOC];
__device__ float g_loss[BATCH];

// ---------------- PTX helpers (portable, compute_103-legal) -----------
__device__ __forceinline__ void ldsm4(uint32_t* r, uint32_t addr) {
    asm volatile("ldmatrix.sync.aligned.m8n8.x4.shared.b16 {%0,%1,%2,%3}, [%4];"
                 : "=r"(r[0]), "=r"(r[1]), "=r"(r[2]), "=r"(r[3]) : "r"(addr));
}
__device__ __forceinline__ void mma16816(float* d, const uint32_t* a,
                                         uint32_t b0, uint32_t b1) {
    asm volatile(
        "mma.sync.aligned.m16n8k16.row.col.f32.bf16.bf16.f32 "
        "{%0,%1,%2,%3}, {%4,%5,%6,%7}, {%8,%9}, {%0,%1,%2,%3};"
        : "+f"(d[0]), "+f"(d[1]), "+f"(d[2]), "+f"(d[3])
        : "r"(a[0]), "r"(a[1]), "r"(a[2]), "r"(a[3]), "r"(b0), "r"(b1));
}

// ---------------- kernel 0a/0b: slot map ------------------------------
__global__ void init_slot_kernel() {
    int i = blockIdx.x * blockDim.x + threadIdx.x;
    if (i < BATCH * VOC) g_slot[i] = -1;
}
__global__ void write_slot_kernel(const int* __restrict__ ys_pad) {
    int b = blockIdx.x;
    int j = threadIdx.x;
    if (j < LMAX) g_slot[b * VOC + ys_pad[b * LMAX + j]] = j + 1;
    if (j == LMAX) g_slot[b * VOC + 0] = 0;
}

// ---------------- kernel 0c: convert A to bf16 -------------------------
__global__ __launch_bounds__(256) void convA_kernel(const float* __restrict__ src) {
    size_t i = (size_t)(blockIdx.x * blockDim.x + threadIdx.x) * 4;
    if (i < (size_t)NROWS * DDIM) {
        float4 v = *(const float4*)(src + i);
        *(__nv_bfloat162*)(g_Abf + i)     = __floats2bfloat162_rn(v.x, v.y);
        *(__nv_bfloat162*)(g_Abf + i + 2) = __floats2bfloat162_rn(v.z, v.w);
    }
}

// ---------------- kernel 0d: transpose W -> [VPAD, DDIM] bf16 ----------
__global__ __launch_bounds__(256) void transW_kernel(const float* __restrict__ W) {
    __shared__ float sm[32][33];
    int v0 = blockIdx.x * 32, k0 = blockIdx.y * 32;
    int tx = threadIdx.x, ty = threadIdx.y;  // 32 x 8
#pragma unroll
    for (int r = 0; r < 4; r++) {
        int k = k0 + ty + r * 8, v = v0 + tx;
        sm[ty + r * 8][tx] = (v < VOC) ? W[(size_t)k * VOC + v] : 0.f;
    }
    __syncthreads();
#pragma unroll
    for (int r = 0; r < 4; r++) {
        int v = v0 + ty + r * 8, k = k0 + tx;
        g_Wt[(size_t)v * DDIM + k] = __float2bfloat16(sm[tx][ty + r * 8]);
    }
}

// ---------------- kernel 1: mma.sync GEMM + fused softmax epilogue -----
// 128x128x32 tiles, 256 threads (8 warps, 2x4), warp tile 64x32.
__global__ __launch_bounds__(256, 1)
void mma_gemm_kernel(const float* __restrict__ bias) {
    // smem: [buf0: A 10240 | B 10240][buf1: A | B] | bias 512 | slots 1024
    __shared__ __align__(16) char sbuf[2 * 2 * TILE_BYTES + 512 + 1024];
    const uint32_t sb = (uint32_t)__cvta_generic_to_shared(sbuf);
    float* bias_s = (float*)(sbuf + 40960);
    int* slot_s   = (int*)(sbuf + 41472);

    const int tid = threadIdx.x;
    const int lane = tid & 31, wid = tid >> 5;
    const int wm = wid >> 2, wn = wid & 3;
    const int n0 = blockIdx.x * 128, m0 = blockIdx.y * 128;
    const int rb0 = m0 / TLEN, rb1 = (m0 + 127) / TLEN;

    if (tid < 128) {
        int gc = n0 + tid;
        bias_s[tid]           = (gc < VOC) ? bias[gc] : 0.f;
        slot_s[tid]           = (gc < VOC) ? g_slot[rb0 * VOC + gc] : -1;
        slot_s[128 + tid]     = (gc < VOC) ? g_slot[rb1 * VOC + gc] : -1;
    }

    // gmem->smem mapping: 2 iters, each thread one 16B chunk per operand
    const int l0 = tid, l1 = tid + 256;  // lin idx: row = lin>>2, chunk = lin&3
    const int r0i = l0 >> 2, c0i = l0 & 3, r1i = l1 >> 2, c1i = l1 & 3;
    const __nv_bfloat16* Ab = g_Abf + (size_t)m0 * DDIM;
    const __nv_bfloat16* Bb = g_Wt  + (size_t)n0 * DDIM;

    float4 ra0, ra1, rbv0, rbv1;
    {
        ra0  = *(const float4*)(Ab + (size_t)r0i * DDIM + c0i * 8);
        ra1  = *(const float4*)(Ab + (size_t)r1i * DDIM + c1i * 8);
        rbv0 = *(const float4*)(Bb + (size_t)r0i * DDIM + c0i * 8);
        rbv1 = *(const float4*)(Bb + (size_t)r1i * DDIM + c1i * 8);
    }

    float acc[4][16];
#pragma unroll
    for (int i = 0; i < 4; i++)
#pragma unroll
        for (int j = 0; j < 16; j++) acc[i][j] = 0.f;

    // ldmatrix lane base offsets (within a tile)
    const uint32_t aRow = (uint32_t)((wm * 64 + (lane & 15)) * RSTB + (lane >> 4) * 16);
    const uint32_t bRow = (uint32_t)((wn * 32 + (lane & 15)) * RSTB + (lane >> 4) * 16) + TILE_BYTES;

    int buf = 0;
    // store chunk 0
    {
        char* A = sbuf; char* B = sbuf + TILE_BYTES;
        *(float4*)(A + r0i * RSTB + c0i * 16) = ra0;
        *(float4*)(A + r1i * RSTB + c1i * 16) = ra1;
        *(float4*)(B + r0i * RSTB + c0i * 16) = rbv0;
        *(float4*)(B + r1i * RSTB + c1i * 16) = rbv1;
    }
    __syncthreads();

    for (int kc = 0; kc < 16; kc++) {
        if (kc < 15) {
            int k0 = (kc + 1) * 32;
            ra0  = *(const float4*)(Ab + (size_t)r0i * DDIM + k0 + c0i * 8);
            ra1  = *(const float4*)(Ab + (size_t)r1i * DDIM + k0 + c1i * 8);
            rbv0 = *(const float4*)(Bb + (size_t)r0i * DDIM + k0 + c0i * 8);
            rbv1 = *(const float4*)(Bb + (size_t)r1i * DDIM + k0 + c1i * 8);
        }
        const uint32_t base = sb + buf * (2 * TILE_BYTES);
#pragma unroll
        for (int h = 0; h < 2; h++) {
            uint32_t af[4][4], bf[2][4];
#pragma unroll
            for (int mf = 0; mf < 4; mf++)
                ldsm4(af[mf], base + aRow + mf * (16 * RSTB) + h * 32);
#pragma unroll
            for (int jg = 0; jg < 2; jg++)
                ldsm4(bf[jg], base + bRow + jg * (16 * RSTB) + h * 32);
#pragma unroll
            for (int mf = 0; mf < 4; mf++) {
#pragma unroll
                for (int jg = 0; jg < 2; jg++) {
                    mma16816(&acc[mf][(jg * 2 + 0) * 4], af[mf], bf[jg][0], bf[jg][2]);
                    mma16816(&acc[mf][(jg * 2 + 1) * 4], af[mf], bf[jg][1], bf[jg][3]);
                }
            }
        }
        if (kc < 15) {
            char* A = sbuf + (buf ^ 1) * (2 * TILE_BYTES);
            char* B = A + TILE_BYTES;
            *(float4*)(A + r0i * RSTB + c0i * 16) = ra0;
            *(float4*)(A + r1i * RSTB + c1i * 16) = ra1;
            *(float4*)(B + r0i * RSTB + c0i * 16) = rbv0;
            *(float4*)(B + r1i * RSTB + c1i * 16) = rbv1;
            __syncthreads();
            buf ^= 1;
        }
    }

    // ---- epilogue ----
    // thread's 8 columns: nf in 0..3, e in 0..1
    float biasv[8]; bool validv[8]; int sl0[8], sl1[8];
#pragma unroll
    for (int nf = 0; nf < 4; nf++)
#pragma unroll
        for (int e = 0; e < 2; e++) {
            int idx = nf * 2 + e;
            int c = wn * 32 + nf * 8 + (lane & 3) * 2 + e;
            biasv[idx]  = bias_s[c];
            validv[idx] = (n0 + c) < VOC;
            sl0[idx] = slot_s[c];
            sl1[idx] = slot_s[128 + c];
        }
#pragma unroll
    for (int mf = 0; mf < 4; mf++)
#pragma unroll
        for (int k = 0; k < 16; k++)
            acc[mf][k] += biasv[(k >> 2) * 2 + (k & 1)];

    __syncthreads();   // tiles done; reuse smem for reductions
    float* redM = (float*)sbuf;          // [128][5]
    float* redS = (float*)(sbuf + 2560); // [128][5]

#pragma unroll
    for (int mf = 0; mf < 4; mf++) {
#pragma unroll
        for (int half = 0; half < 2; half++) {
            int r = wm * 64 + mf * 16 + half * 8 + (lane >> 2);
            int grow = m0 + r;
            int bb = (rb1 > rb0 && grow >= rb1 * TLEN) ? 1 : 0;
            float m = -3.4e38f, s = 0.f;
#pragma unroll
            for (int nf = 0; nf < 4; nf++)
#pragma unroll
                for (int e = 0; e < 2; e++) {
                    float v = acc[mf][nf * 4 + half * 2 + e];
                    if (validv[nf * 2 + e]) m = fmaxf(m, v);
                }
#pragma unroll
            for (int nf = 0; nf < 4; nf++)
#pragma unroll
                for (int e = 0; e < 2; e++) {
                    int ci = nf * 2 + e;
                    float v = acc[mf][nf * 4 + half * 2 + e];
                    if (validv[ci]) {
                        s += __expf(v - m);
                        int sl = bb ? sl1[ci] : sl0[ci];
                        if (sl >= 0) g_gath[(size_t)grow * GSTRIDE + sl] = v;
                    }
                }
            // quad reduce (lanes l, l^1, l^2 share the row)
#pragma unroll
            for (int off = 1; off <= 2; off <<= 1) {
                float om = __shfl_xor_sync(~0u, m, off);
                float os = __shfl_xor_sync(~0u, s, off);
                float nm = fmaxf(m, om);
                s = s * __expf(m - nm) + os * __expf(om - nm);
                m = nm;
            }
            if ((lane & 3) == 0) { redM[r * 5 + wn] = m; redS[r * 5 + wn] = s; }
        }
    }
    __syncthreads();
    if (tid < 128) {
        float M = redM[tid * 5 + 0], S = redS[tid * 5 + 0];
#pragma unroll
        for (int w = 1; w < 4; w++) {
            float m2 = redM[tid * 5 + w], s2 = redS[tid * 5 + w];
            float Mn = fmaxf(M, m2);
            S = S * __expf(M - Mn) + s2 * __expf(m2 - Mn);
            M = Mn;
        }
        g_pmax[(m0 + tid) * NTILES + blockIdx.x] = M;
        g_psum[(m0 + tid) * NTILES + blockIdx.x] = S;
    }
}

// ---------------- kernel 2: fused LSE reduce + emit expand -------------
__global__ __launch_bounds__(128) void emit_kernel(const int* __restrict__ ys_pad) {
    const int row = blockIdx.x;
    const int tid = threadIdx.x;
    __shared__ float lse_s;
    if (tid < 32) {
        float pm = g_pmax[row * NTILES + tid];
        float ps = g_psum[row * NTILES + tid];
        float M = pm;
#pragma unroll
        for (int o = 16; o; o >>= 1) M = fmaxf(M, __shfl_xor_sync(~0u, M, o));
        float v = ps * __expf(pm - M);
#pragma unroll
        for (int o = 16; o; o >>= 1) v += __shfl_xor_sync(~0u, v, o);
        if (tid == 0) lse_s = M + __logf(v);
    }
    __syncthreads();
    if (tid < NEMIT) {
        int b = row / TLEN;
        int col = (tid == 0) ? 0 : ys_pad[b * LMAX + tid - 1];
        int slot = g_slot[b * VOC + col];
        g_emit[(size_t)row * NEMIT + tid] = g_gath[(size_t)row * GSTRIDE + slot] - lse_s;
    }
}

// ---------------- kernel 3: CTC forward recursion ----------------------
__global__ __launch_bounds__(224) void ctc_kernel(const int* __restrict__ hlens,
                                                  const int* __restrict__ ys_pad,
                                                  const int* __restrict__ ys_lens) {
    const int b = blockIdx.x;
    const int s = threadIdx.x;
    __shared__ float al[2][SEXT + 2];

    const float* eb = g_emit + (size_t)b * TLEN * NEMIT;
    const bool act = s < SEXT;
    const int j = (s & 1) ? ((s >> 1) + 1) : 0;

    bool skip = false;
    if (act && (s & 1) && s >= 3) {
        int cur  = ys_pad[b * LMAX + (s >> 1)];
        int prev = ys_pad[b * LMAX + (s >> 1) - 1];
        skip = (cur != prev);
    }

    if (s < 2) { al[0][s] = NEGV; al[1][s] = NEGV; }
    if (act) al[0][s + 2] = (s < 2) ? eb[j] : NEGV;

    const int hl = hlens[b];
    float e1 = NEGV;
    if (act && hl > 1) e1 = eb[NEMIT + j];
    __syncthreads();

    int p = 0;
    for (int t = 1; t < hl; t++) {
        float e = e1;
        if (act && t + 1 < hl) e1 = eb[(size_t)(t + 1) * NEMIT + j];

        if (act) {
            float a0 = al[p][s + 2];
            float a1 = al[p][s + 1];
            float a2 = skip ? al[p][s] : NEGV;
            float m = fmaxf(a0, fmaxf(a1, a2));
            float w = __expf(a0 - m) + __expf(a1 - m) + __expf(a2 - m);
            al[1 - p][s + 2] = m + __logf(w) + e;
        }
        __syncthreads();
        p ^= 1;
    }

    if (s == 0) {
        int L = ys_lens[b];
        int idx = 2 * L;
        float aL = al[p][idx + 2];
        float aP = al[p][idx + 1];
        float m = fmaxf(aL, aP);
        float loss = -(m + __logf(__expf(aL - m) + __expf(aP - m)));
        if (!isfinite(loss) || loss >= 1e29f) loss = 0.f;
        g_loss[b] = loss;
    }
}

// ---------------- kernel 4: final reduce --------------------------------
__global__ void finalize_kernel(float* __restrict__ out) {
    float sum = 0.f;
    for (int i = 0; i < BATCH; i++) sum += g_loss[i];
    out[0] = sum / (float)BATCH;
}

// ---------------- launch --------------------------------------------------
extern "C" void kernel_launch(void* const* d_in, const int* in_sizes, int n_in,
                              void* d_out, int out_size) {
    const float* hs     = (const float*)d_in[0];
    const float* Wm     = (const float*)d_in[1];
    const float* bias   = (const float*)d_in[2];
    const int* hlens    = (const int*)d_in[3];
    const int* ys_pad   = (const int*)d_in[4];
    const int* ys_lens  = (const int*)d_in[5];
    float* out = (float*)d_out;

    init_slot_kernel<<<(BATCH * VOC + 255) / 256, 256>>>();
    write_slot_kernel<<<BATCH, 128>>>(ys_pad);
    convA_kernel<<<(NROWS * DDIM / 4 + 255) / 256, 256>>>(hs);
    transW_kernel<<<dim3(VPAD / 32, DDIM / 32), dim3(32, 8)>>>(Wm);

    dim3 gemm_grid(NTILES, NROWS / 128);  // (32, 100)
    mma_gemm_kernel<<<gemm_grid, 256>>>(bias);

    emit_kernel<<<NROWS, 128>>>(ys_pad);
    ctc_kernel<<<BATCH, 224>>>(hlens, ys_pad, ys_lens);
    finalize_kernel<<<1, 1>>>(out);
}

// round 5
// speedup vs baseline: 3.0434x; 1.1371x over previous
#include <cuda_runtime.h>
#include <cuda_bf16.h>
#include <math.h>
#include <stdint.h>

#define BATCH 16
#define TLEN 800
#define DDIM 512
#define VOC 4000
#define VPAD 4096
#define LMAX 100
#define SEXT 201
#define NEMIT 101
#define NROWS (BATCH * TLEN)
#define NTILES 32
#define GSTRIDE 104
#define NEGV (-1e30f)

#define RSTB 80            // smem row stride in bytes (40 bf16)
#define TILE_BYTES 10240   // 128 rows * 80 B
#define STAGE_BYTES 20480  // A tile + B tile
#define NSTAGE 4
#define DYN_SMEM (NSTAGE * STAGE_BYTES)   // 81920

// ---------------- device scratch ----------------
__device__ __align__(16) __nv_bfloat16 g_Abf[(size_t)NROWS * DDIM];
__device__ __align__(16) __nv_bfloat16 g_Wt[(size_t)VPAD * DDIM];
__device__ float g_pmax[NROWS * NTILES];
__device__ float g_psum[NROWS * NTILES];
__device__ float g_gath[(size_t)NROWS * GSTRIDE];
__device__ float g_emit[(size_t)NROWS * NEMIT];
__device__ int   g_slot[BATCH * VOC];
__device__ float g_loss[BATCH];

// ---------------- PTX helpers (compute_103-legal) ----------------------
__device__ __forceinline__ void ldsm4(uint32_t* r, uint32_t addr) {
    asm volatile("ldmatrix.sync.aligned.m8n8.x4.shared.b16 {%0,%1,%2,%3}, [%4];"
                 : "=r"(r[0]), "=r"(r[1]), "=r"(r[2]), "=r"(r[3]) : "r"(addr));
}
__device__ __forceinline__ void mma16816(float* d, const uint32_t* a,
                                         uint32_t b0, uint32_t b1) {
    asm volatile(
        "mma.sync.aligned.m16n8k16.row.col.f32.bf16.bf16.f32 "
        "{%0,%1,%2,%3}, {%4,%5,%6,%7}, {%8,%9}, {%0,%1,%2,%3};"
        : "+f"(d[0]), "+f"(d[1]), "+f"(d[2]), "+f"(d[3])
        : "r"(a[0]), "r"(a[1]), "r"(a[2]), "r"(a[3]), "r"(b0), "r"(b1));
}
#define CP16(dst, src) \
    asm volatile("cp.async.cg.shared.global [%0], [%1], 16;" :: "r"(dst), "l"(src))
#define CPCOMMIT() asm volatile("cp.async.commit_group;")
#define CPWAIT2()  asm volatile("cp.async.wait_group 2;")

// ---------------- kernel 0a/0b: slot map ------------------------------
__global__ void init_slot_kernel() {
    int i = blockIdx.x * blockDim.x + threadIdx.x;
    if (i < BATCH * VOC) g_slot[i] = -1;
}
__global__ void write_slot_kernel(const int* __restrict__ ys_pad) {
    int b = blockIdx.x;
    int j = threadIdx.x;
    if (j < LMAX) g_slot[b * VOC + ys_pad[b * LMAX + j]] = j + 1;
    if (j == LMAX) g_slot[b * VOC + 0] = 0;
}

// ---------------- kernel 0c: convert A to bf16 -------------------------
__global__ __launch_bounds__(256) void convA_kernel(const float* __restrict__ src) {
    size_t i = (size_t)(blockIdx.x * blockDim.x + threadIdx.x) * 4;
    if (i < (size_t)NROWS * DDIM) {
        float4 v = *(const float4*)(src + i);
        *(__nv_bfloat162*)(g_Abf + i)     = __floats2bfloat162_rn(v.x, v.y);
        *(__nv_bfloat162*)(g_Abf + i + 2) = __floats2bfloat162_rn(v.z, v.w);
    }
}

// ---------------- kernel 0d: transpose W -> [VPAD, DDIM] bf16 ----------
__global__ __launch_bounds__(256) void transW_kernel(const float* __restrict__ W) {
    __shared__ float sm[32][33];
    int v0 = blockIdx.x * 32, k0 = blockIdx.y * 32;
    int tx = threadIdx.x, ty = threadIdx.y;  // 32 x 8
#pragma unroll
    for (int r = 0; r < 4; r++) {
        int k = k0 + ty + r * 8, v = v0 + tx;
        sm[ty + r * 8][tx] = (v < VOC) ? W[(size_t)k * VOC + v] : 0.f;
    }
    __syncthreads();
#pragma unroll
    for (int r = 0; r < 4; r++) {
        int v = v0 + ty + r * 8, k = k0 + tx;
        g_Wt[(size_t)v * DDIM + k] = __float2bfloat16(sm[tx][ty + r * 8]);
    }
}

// ---------------- kernel 1: cp.async-pipelined mma.sync GEMM -----------
// 128x128x32 tiles, 256 threads (8 warps, 2x4), warp tile 64x32, 4 stages.
__global__ __launch_bounds__(256)
void mma_gemm_kernel(const float* __restrict__ bias) {
    extern __shared__ __align__(128) char dynbuf[];
    __shared__ float bias_s[128];
    __shared__ int   slot_s[256];
    __shared__ float redM[128 * 5];
    __shared__ float redS[128 * 5];

    const uint32_t sbD = (uint32_t)__cvta_generic_to_shared(dynbuf);
    const int tid = threadIdx.x;
    const int lane = tid & 31, wid = tid >> 5;
    const int wm = wid >> 2, wn = wid & 3;
    const int n0 = blockIdx.x * 128, m0 = blockIdx.y * 128;
    const int rb0 = m0 / TLEN, rb1 = (m0 + 127) / TLEN;

    if (tid < 128) {
        int gc = n0 + tid;
        bias_s[tid]       = (gc < VOC) ? bias[gc] : 0.f;
        slot_s[tid]       = (gc < VOC) ? g_slot[rb0 * VOC + gc] : -1;
        slot_s[128 + tid] = (gc < VOC) ? g_slot[rb1 * VOC + gc] : -1;
    }

    // gmem->smem chunk mapping: each thread moves 2 chunks of A, 2 of B
    const int r0i = tid >> 2,        c0i = tid & 3;
    const int r1i = (tid + 256) >> 2, c1i = (tid + 256) & 3;
    const __nv_bfloat16* Ab = g_Abf + (size_t)m0 * DDIM;
    const __nv_bfloat16* Bb = g_Wt  + (size_t)n0 * DDIM;

    // prologue: issue stages 0..2
#pragma unroll
    for (int s = 0; s < NSTAGE - 1; s++) {
        uint32_t dst = sbD + s * STAGE_BYTES;
        int k0 = s * 32;
        CP16(dst + r0i * RSTB + c0i * 16,              Ab + (size_t)r0i * DDIM + k0 + c0i * 8);
        CP16(dst + r1i * RSTB + c1i * 16,              Ab + (size_t)r1i * DDIM + k0 + c1i * 8);
        CP16(dst + TILE_BYTES + r0i * RSTB + c0i * 16, Bb + (size_t)r0i * DDIM + k0 + c0i * 8);
        CP16(dst + TILE_BYTES + r1i * RSTB + c1i * 16, Bb + (size_t)r1i * DDIM + k0 + c1i * 8);
        CPCOMMIT();
    }

    float acc[4][16];
#pragma unroll
    for (int i = 0; i < 4; i++)
#pragma unroll
        for (int j = 0; j < 16; j++) acc[i][j] = 0.f;

    const uint32_t aRow = (uint32_t)((wm * 64 + (lane & 15)) * RSTB + (lane >> 4) * 16);
    const uint32_t bRow = (uint32_t)((wn * 32 + (lane & 15)) * RSTB + (lane >> 4) * 16) + TILE_BYTES;

    for (int kc = 0; kc < 16; kc++) {
        CPWAIT2();            // stage kc complete (this thread)
        __syncthreads();      // all threads' stage kc visible; prior reads done

        // issue stage kc+3 into buffer (kc+3)&3 (== buffer of stage kc-1, safe)
        int ks = kc + NSTAGE - 1;
        if (ks < 16) {
            uint32_t dst = sbD + (ks & 3) * STAGE_BYTES;
            int k0 = ks * 32;
            CP16(dst + r0i * RSTB + c0i * 16,              Ab + (size_t)r0i * DDIM + k0 + c0i * 8);
            CP16(dst + r1i * RSTB + c1i * 16,              Ab + (size_t)r1i * DDIM + k0 + c1i * 8);
            CP16(dst + TILE_BYTES + r0i * RSTB + c0i * 16, Bb + (size_t)r0i * DDIM + k0 + c0i * 8);
            CP16(dst + TILE_BYTES + r1i * RSTB + c1i * 16, Bb + (size_t)r1i * DDIM + k0 + c1i * 8);
        }
        CPCOMMIT();           // always commit (possibly empty) to keep wait counts exact

        const uint32_t base = sbD + (kc & 3) * STAGE_BYTES;
#pragma unroll
        for (int h = 0; h < 2; h++) {
            uint32_t af[4][4], bf[2][4];
#pragma unroll
            for (int mf = 0; mf < 4; mf++)
                ldsm4(af[mf], base + aRow + mf * (16 * RSTB) + h * 32);
#pragma unroll
            for (int jg = 0; jg < 2; jg++)
                ldsm4(bf[jg], base + bRow + jg * (16 * RSTB) + h * 32);
#pragma unroll
            for (int mf = 0; mf < 4; mf++) {
#pragma unroll
                for (int jg = 0; jg < 2; jg++) {
                    mma16816(&acc[mf][(jg * 2 + 0) * 4], af[mf], bf[jg][0], bf[jg][2]);
                    mma16816(&acc[mf][(jg * 2 + 1) * 4], af[mf], bf[jg][1], bf[jg][3]);
                }
            }
        }
    }

    // ---- epilogue: bias + online max/sumexp + label gather ----
    float biasv[8]; bool validv[8]; int sl0[8], sl1[8];
#pragma unroll
    for (int nf = 0; nf < 4; nf++)
#pragma unroll
        for (int e = 0; e < 2; e++) {
            int idx = nf * 2 + e;
            int c = wn * 32 + nf * 8 + (lane & 3) * 2 + e;
            biasv[idx]  = bias_s[c];
            validv[idx] = (n0 + c) < VOC;
            sl0[idx] = slot_s[c];
            sl1[idx] = slot_s[128 + c];
        }
#pragma unroll
    for (int mf = 0; mf < 4; mf++)
#pragma unroll
        for (int k = 0; k < 16; k++)
            acc[mf][k] += biasv[(k >> 2) * 2 + (k & 1)];

#pragma unroll
    for (int mf = 0; mf < 4; mf++) {
#pragma unroll
        for (int half = 0; half < 2; half++) {
            int r = wm * 64 + mf * 16 + half * 8 + (lane >> 2);
            int grow = m0 + r;
            int bb = (rb1 > rb0 && grow >= rb1 * TLEN) ? 1 : 0;
            float m = -3.4e38f, s = 0.f;
#pragma unroll
            for (int nf = 0; nf < 4; nf++)
#pragma unroll
                for (int e = 0; e < 2; e++) {
                    float v = acc[mf][nf * 4 + half * 2 + e];
                    if (validv[nf * 2 + e]) m = fmaxf(m, v);
                }
#pragma unroll
            for (int nf = 0; nf < 4; nf++)
#pragma unroll
                for (int e = 0; e < 2; e++) {
                    int ci = nf * 2 + e;
                    float v = acc[mf][nf * 4 + half * 2 + e];
                    if (validv[ci]) {
                        s += __expf(v - m);
                        int sl = bb ? sl1[ci] : sl0[ci];
                        if (sl >= 0) g_gath[(size_t)grow * GSTRIDE + sl] = v;
                    }
                }
#pragma unroll
            for (int off = 1; off <= 2; off <<= 1) {
                float om = __shfl_xor_sync(~0u, m, off);
                float os = __shfl_xor_sync(~0u, s, off);
                float nm = fmaxf(m, om);
                s = s * __expf(m - nm) + os * __expf(om - nm);
                m = nm;
            }
            if ((lane & 3) == 0) { redM[r * 5 + wn] = m; redS[r * 5 + wn] = s; }
        }
    }
    __syncthreads();
    if (tid < 128) {
        float M = redM[tid * 5 + 0], S = redS[tid * 5 + 0];
#pragma unroll
        for (int w = 1; w < 4; w++) {
            float m2 = redM[tid * 5 + w], s2 = redS[tid * 5 + w];
            float Mn = fmaxf(M, m2);
            S = S * __expf(M - Mn) + s2 * __expf(m2 - Mn);
            M = Mn;
        }
        g_pmax[(m0 + tid) * NTILES + blockIdx.x] = M;
        g_psum[(m0 + tid) * NTILES + blockIdx.x] = S;
    }
}

// ---------------- kernel 2: fused LSE reduce + emit expand -------------
__global__ __launch_bounds__(128) void emit_kernel(const int* __restrict__ ys_pad) {
    const int row = blockIdx.x;
    const int tid = threadIdx.x;
    __shared__ float lse_s;
    if (tid < 32) {
        float pm = g_pmax[row * NTILES + tid];
        float ps = g_psum[row * NTILES + tid];
        float M = pm;
#pragma unroll
        for (int o = 16; o; o >>= 1) M = fmaxf(M, __shfl_xor_sync(~0u, M, o));
        float v = ps * __expf(pm - M);
#pragma unroll
        for (int o = 16; o; o >>= 1) v += __shfl_xor_sync(~0u, v, o);
        if (tid == 0) lse_s = M + __logf(v);
    }
    __syncthreads();
    if (tid < NEMIT) {
        int b = row / TLEN;
        int col = (tid == 0) ? 0 : ys_pad[b * LMAX + tid - 1];
        int slot = g_slot[b * VOC + col];
        g_emit[(size_t)row * NEMIT + tid] = g_gath[(size_t)row * GSTRIDE + slot] - lse_s;
    }
}

// ---------------- kernel 3: CTC forward recursion ----------------------
__global__ __launch_bounds__(224) void ctc_kernel(const int* __restrict__ hlens,
                                                  const int* __restrict__ ys_pad,
                                                  const int* __restrict__ ys_lens) {
    const int b = blockIdx.x;
    const int s = threadIdx.x;
    __shared__ float al[2][SEXT + 2];

    const float* eb = g_emit + (size_t)b * TLEN * NEMIT;
    const bool act = s < SEXT;
    const int j = (s & 1) ? ((s >> 1) + 1) : 0;

    bool skip = false;
    if (act && (s & 1) && s >= 3) {
        int cur  = ys_pad[b * LMAX + (s >> 1)];
        int prev = ys_pad[b * LMAX + (s >> 1) - 1];
        skip = (cur != prev);
    }

    if (s < 2) { al[0][s] = NEGV; al[1][s] = NEGV; }
    if (act) al[0][s + 2] = (s < 2) ? eb[j] : NEGV;

    const int hl = hlens[b];
    float e1 = NEGV;
    if (act && hl > 1) e1 = eb[NEMIT + j];
    __syncthreads();

    int p = 0;
    for (int t = 1; t < hl; t++) {
        float e = e1;
        if (act && t + 1 < hl) e1 = eb[(size_t)(t + 1) * NEMIT + j];

        if (act) {
            float a0 = al[p][s + 2];
            float a1 = al[p][s + 1];
            float a2 = skip ? al[p][s] : NEGV;
            float m = fmaxf(a0, fmaxf(a1, a2));
            float w = __expf(a0 - m) + __expf(a1 - m) + __expf(a2 - m);
            al[1 - p][s + 2] = m + __logf(w) + e;
        }
        __syncthreads();
        p ^= 1;
    }

    if (s == 0) {
        int L = ys_lens[b];
        int idx = 2 * L;
        float aL = al[p][idx + 2];
        float aP = al[p][idx + 1];
        float m = fmaxf(aL, aP);
        float loss = -(m + __logf(__expf(aL - m) + __expf(aP - m)));
        if (!isfinite(loss) || loss >= 1e29f) loss = 0.f;
        g_loss[b] = loss;
    }
}

// ---------------- kernel 4: final reduce --------------------------------
__global__ void finalize_kernel(float* __restrict__ out) {
    float sum = 0.f;
    for (int i = 0; i < BATCH; i++) sum += g_loss[i];
    out[0] = sum / (float)BATCH;
}

// ---------------- launch --------------------------------------------------
extern "C" void kernel_launch(void* const* d_in, const int* in_sizes, int n_in,
                              void* d_out, int out_size) {
    const float* hs     = (const float*)d_in[0];
    const float* Wm     = (const float*)d_in[1];
    const float* bias   = (const float*)d_in[2];
    const int* hlens    = (const int*)d_in[3];
    const int* ys_pad   = (const int*)d_in[4];
    const int* ys_lens  = (const int*)d_in[5];
    float* out = (float*)d_out;

    static int configured = 0;
    if (!configured) {
        cudaFuncSetAttribute(mma_gemm_kernel,
                             cudaFuncAttributeMaxDynamicSharedMemorySize, DYN_SMEM);
        configured = 1;
    }

    init_slot_kernel<<<(BATCH * VOC + 255) / 256, 256>>>();
    write_slot_kernel<<<BATCH, 128>>>(ys_pad);
    convA_kernel<<<(NROWS * DDIM / 4 + 255) / 256, 256>>>(hs);
    transW_kernel<<<dim3(VPAD / 32, DDIM / 32), dim3(32, 8)>>>(Wm);

    dim3 gemm_grid(NTILES, NROWS / 128);  // (32, 100)
    mma_gemm_kernel<<<gemm_grid, 256, DYN_SMEM>>>(bias);

    emit_kernel<<<NROWS, 128>>>(ys_pad);
    ctc_kernel<<<BATCH, 224>>>(hlens, ys_pad, ys_lens);
    finalize_kernel<<<1, 1>>>(out);
}

// round 6
// speedup vs baseline: 3.1980x; 1.0508x over previous
#include <cuda_runtime.h>
#include <cuda_bf16.h>
#include <math.h>
#include <stdint.h>

#define BATCH 16
#define TLEN 800
#define DDIM 512
#define VOC 4000
#define VPAD 4096
#define LMAX 100
#define SEXT 201
#define NEMIT 101
#define NROWS (BATCH * TLEN)
#define NTILES 32
#define GSTRIDE 104
#define NEGV (-1e30f)

#define RSTB 80            // smem row stride in bytes (40 bf16)
#define TILE_BYTES 10240   // 128 rows * 80 B
#define STAGE_BYTES 20480  // A tile + B tile
#define NSTAGE 4
#define DYN_SMEM (NSTAGE * STAGE_BYTES)   // 81920

// ---------------- device scratch ----------------
__device__ __align__(16) __nv_bfloat16 g_Abf[(size_t)NROWS * DDIM];
__device__ __align__(16) __nv_bfloat16 g_Wt[(size_t)VPAD * DDIM];
__device__ float g_pmax[NROWS * NTILES];
__device__ float g_psum[NROWS * NTILES];
__device__ float g_gath[(size_t)NROWS * GSTRIDE];
__device__ float g_emit[(size_t)NROWS * NEMIT];
__device__ int   g_slot[BATCH * VOC];
__device__ float g_loss[BATCH];

// ---------------- PTX helpers (compute_103-legal) ----------------------
__device__ __forceinline__ void ldsm4(uint32_t* r, uint32_t addr) {
    asm volatile("ldmatrix.sync.aligned.m8n8.x4.shared.b16 {%0,%1,%2,%3}, [%4];"
                 : "=r"(r[0]), "=r"(r[1]), "=r"(r[2]), "=r"(r[3]) : "r"(addr));
}
__device__ __forceinline__ void mma16816(float* d, const uint32_t* a,
                                         uint32_t b0, uint32_t b1) {
    asm volatile(
        "mma.sync.aligned.m16n8k16.row.col.f32.bf16.bf16.f32 "
        "{%0,%1,%2,%3}, {%4,%5,%6,%7}, {%8,%9}, {%0,%1,%2,%3};"
        : "+f"(d[0]), "+f"(d[1]), "+f"(d[2]), "+f"(d[3])
        : "r"(a[0]), "r"(a[1]), "r"(a[2]), "r"(a[3]), "r"(b0), "r"(b1));
}
#define CP16(dst, src) \
    asm volatile("cp.async.cg.shared.global [%0], [%1], 16;" :: "r"(dst), "l"(src))
#define CPCOMMIT() asm volatile("cp.async.commit_group;")
#define CPWAIT2()  asm volatile("cp.async.wait_group 2;")

// ---------------- kernel 0a/0b: slot map ------------------------------
__global__ void init_slot_kernel() {
    int i = blockIdx.x * blockDim.x + threadIdx.x;
    if (i < BATCH * VOC) g_slot[i] = -1;
}
__global__ void write_slot_kernel(const int* __restrict__ ys_pad) {
    int b = blockIdx.x;
    int j = threadIdx.x;
    if (j < LMAX) g_slot[b * VOC + ys_pad[b * LMAX + j]] = j + 1;
    if (j == LMAX) g_slot[b * VOC + 0] = 0;
}

// ---------------- kernel 0c: convert A to bf16 -------------------------
__global__ __launch_bounds__(256) void convA_kernel(const float* __restrict__ src) {
    size_t i = (size_t)(blockIdx.x * blockDim.x + threadIdx.x) * 4;
    if (i < (size_t)NROWS * DDIM) {
        float4 v = *(const float4*)(src + i);
        *(__nv_bfloat162*)(g_Abf + i)     = __floats2bfloat162_rn(v.x, v.y);
        *(__nv_bfloat162*)(g_Abf + i + 2) = __floats2bfloat162_rn(v.z, v.w);
    }
}

// ---------------- kernel 0d: transpose W -> [VPAD, DDIM] bf16 ----------
__global__ __launch_bounds__(256) void transW_kernel(const float* __restrict__ W) {
    __shared__ float sm[32][33];
    int v0 = blockIdx.x * 32, k0 = blockIdx.y * 32;
    int tx = threadIdx.x, ty = threadIdx.y;  // 32 x 8
#pragma unroll
    for (int r = 0; r < 4; r++) {
        int k = k0 + ty + r * 8, v = v0 + tx;
        sm[ty + r * 8][tx] = (v < VOC) ? W[(size_t)k * VOC + v] : 0.f;
    }
    __syncthreads();
#pragma unroll
    for (int r = 0; r < 4; r++) {
        int v = v0 + ty + r * 8, k = k0 + tx;
        g_Wt[(size_t)v * DDIM + k] = __float2bfloat16(sm[tx][ty + r * 8]);
    }
}

// ---------------- kernel 1: cp.async-pipelined mma.sync GEMM -----------
// 128x128x32 tiles, 256 threads (8 warps, 2x4), warp tile 64x32, 4 stages,
// 2 CTAs/SM (regs capped at 128 via launch bounds).
__global__ __launch_bounds__(256, 2)
void mma_gemm_kernel(const float* __restrict__ bias) {
    extern __shared__ __align__(128) char dynbuf[];
    __shared__ float bias_s[128];
    __shared__ int   slot_s[256];
    __shared__ float redM[128 * 5];
    __shared__ float redS[128 * 5];

    const uint32_t sbD = (uint32_t)__cvta_generic_to_shared(dynbuf);
    const int tid = threadIdx.x;
    const int lane = tid & 31, wid = tid >> 5;
    const int wm = wid >> 2, wn = wid & 3;
    const int n0 = blockIdx.x * 128, m0 = blockIdx.y * 128;
    const int rb0 = m0 / TLEN, rb1 = (m0 + 127) / TLEN;

    if (tid < 128) {
        int gc = n0 + tid;
        bias_s[tid]       = (gc < VOC) ? bias[gc] : 0.f;
        slot_s[tid]       = (gc < VOC) ? g_slot[rb0 * VOC + gc] : -1;
        slot_s[128 + tid] = (gc < VOC) ? g_slot[rb1 * VOC + gc] : -1;
    }

    // gmem->smem chunk mapping: each thread moves 2 chunks of A, 2 of B
    const int r0i = tid >> 2,        c0i = tid & 3;
    const int r1i = (tid + 256) >> 2, c1i = (tid + 256) & 3;
    const __nv_bfloat16* Ab = g_Abf + (size_t)m0 * DDIM;
    const __nv_bfloat16* Bb = g_Wt  + (size_t)n0 * DDIM;

    // prologue: issue stages 0..2
#pragma unroll
    for (int s = 0; s < NSTAGE - 1; s++) {
        uint32_t dst = sbD + s * STAGE_BYTES;
        int k0 = s * 32;
        CP16(dst + r0i * RSTB + c0i * 16,              Ab + (size_t)r0i * DDIM + k0 + c0i * 8);
        CP16(dst + r1i * RSTB + c1i * 16,              Ab + (size_t)r1i * DDIM + k0 + c1i * 8);
        CP16(dst + TILE_BYTES + r0i * RSTB + c0i * 16, Bb + (size_t)r0i * DDIM + k0 + c0i * 8);
        CP16(dst + TILE_BYTES + r1i * RSTB + c1i * 16, Bb + (size_t)r1i * DDIM + k0 + c1i * 8);
        CPCOMMIT();
    }

    float acc[4][16];
#pragma unroll
    for (int i = 0; i < 4; i++)
#pragma unroll
        for (int j = 0; j < 16; j++) acc[i][j] = 0.f;

    const uint32_t aRow = (uint32_t)((wm * 64 + (lane & 15)) * RSTB + (lane >> 4) * 16);
    const uint32_t bRow = (uint32_t)((wn * 32 + (lane & 15)) * RSTB + (lane >> 4) * 16) + TILE_BYTES;

    for (int kc = 0; kc < 16; kc++) {
        CPWAIT2();            // stage kc complete (this thread)
        __syncthreads();      // all threads' stage kc visible; prior reads done

        // issue stage kc+3 into buffer (kc+3)&3 (== buffer of stage kc-1, safe)
        int ks = kc + NSTAGE - 1;
        if (ks < 16) {
            uint32_t dst = sbD + (ks & 3) * STAGE_BYTES;
            int k0 = ks * 32;
            CP16(dst + r0i * RSTB + c0i * 16,              Ab + (size_t)r0i * DDIM + k0 + c0i * 8);
            CP16(dst + r1i * RSTB + c1i * 16,              Ab + (size_t)r1i * DDIM + k0 + c1i * 8);
            CP16(dst + TILE_BYTES + r0i * RSTB + c0i * 16, Bb + (size_t)r0i * DDIM + k0 + c0i * 8);
            CP16(dst + TILE_BYTES + r1i * RSTB + c1i * 16, Bb + (size_t)r1i * DDIM + k0 + c1i * 8);
        }
        CPCOMMIT();           // always commit (possibly empty) to keep wait counts exact

        const uint32_t base = sbD + (kc & 3) * STAGE_BYTES;
#pragma unroll
        for (int h = 0; h < 2; h++) {
            uint32_t af[4][4], bf[2][4];
#pragma unroll
            for (int mf = 0; mf < 4; mf++)
                ldsm4(af[mf], base + aRow + mf * (16 * RSTB) + h * 32);
#pragma unroll
            for (int jg = 0; jg < 2; jg++)
                ldsm4(bf[jg], base + bRow + jg * (16 * RSTB) + h * 32);
#pragma unroll
            for (int mf = 0; mf < 4; mf++) {
#pragma unroll
                for (int jg = 0; jg < 2; jg++) {
                    mma16816(&acc[mf][(jg * 2 + 0) * 4], af[mf], bf[jg][0], bf[jg][2]);
                    mma16816(&acc[mf][(jg * 2 + 1) * 4], af[mf], bf[jg][1], bf[jg][3]);
                }
            }
        }
    }

    // ---- epilogue: bias + online max/sumexp + label gather ----
    float biasv[8]; bool validv[8]; int sl0[8], sl1[8];
#pragma unroll
    for (int nf = 0; nf < 4; nf++)
#pragma unroll
        for (int e = 0; e < 2; e++) {
            int idx = nf * 2 + e;
            int c = wn * 32 + nf * 8 + (lane & 3) * 2 + e;
            biasv[idx]  = bias_s[c];
            validv[idx] = (n0 + c) < VOC;
            sl0[idx] = slot_s[c];
            sl1[idx] = slot_s[128 + c];
        }
#pragma unroll
    for (int mf = 0; mf < 4; mf++)
#pragma unroll
        for (int k = 0; k < 16; k++)
            acc[mf][k] += biasv[(k >> 2) * 2 + (k & 1)];

#pragma unroll
    for (int mf = 0; mf < 4; mf++) {
#pragma unroll
        for (int half = 0; half < 2; half++) {
            int r = wm * 64 + mf * 16 + half * 8 + (lane >> 2);
            int grow = m0 + r;
            int bb = (rb1 > rb0 && grow >= rb1 * TLEN) ? 1 : 0;
            float m = -3.4e38f, s = 0.f;
#pragma unroll
            for (int nf = 0; nf < 4; nf++)
#pragma unroll
                for (int e = 0; e < 2; e++) {
                    float v = acc[mf][nf * 4 + half * 2 + e];
                    if (validv[nf * 2 + e]) m = fmaxf(m, v);
                }
#pragma unroll
            for (int nf = 0; nf < 4; nf++)
#pragma unroll
                for (int e = 0; e < 2; e++) {
                    int ci = nf * 2 + e;
                    float v = acc[mf][nf * 4 + half * 2 + e];
                    if (validv[ci]) {
                        s += __expf(v - m);
                        int sl = bb ? sl1[ci] : sl0[ci];
                        if (sl >= 0) g_gath[(size_t)grow * GSTRIDE + sl] = v;
                    }
                }
#pragma unroll
            for (int off = 1; off <= 2; off <<= 1) {
                float om = __shfl_xor_sync(~0u, m, off);
                float os = __shfl_xor_sync(~0u, s, off);
                float nm = fmaxf(m, om);
                s = s * __expf(m - nm) + os * __expf(om - nm);
                m = nm;
            }
            if ((lane & 3) == 0) { redM[r * 5 + wn] = m; redS[r * 5 + wn] = s; }
        }
    }
    __syncthreads();
    if (tid < 128) {
        float M = redM[tid * 5 + 0], S = redS[tid * 5 + 0];
#pragma unroll
        for (int w = 1; w < 4; w++) {
            float m2 = redM[tid * 5 + w], s2 = redS[tid * 5 + w];
            float Mn = fmaxf(M, m2);
            S = S * __expf(M - Mn) + s2 * __expf(m2 - Mn);
            M = Mn;
        }
        g_pmax[(m0 + tid) * NTILES + blockIdx.x] = M;
        g_psum[(m0 + tid) * NTILES + blockIdx.x] = S;
    }
}

// ---------------- kernel 2: fused LSE reduce + emit expand -------------
__global__ __launch_bounds__(128) void emit_kernel(const int* __restrict__ ys_pad) {
    const int row = blockIdx.x;
    const int tid = threadIdx.x;
    __shared__ float lse_s;
    if (tid < 32) {
        float pm = g_pmax[row * NTILES + tid];
        float ps = g_psum[row * NTILES + tid];
        float M = pm;
#pragma unroll
        for (int o = 16; o; o >>= 1) M = fmaxf(M, __shfl_xor_sync(~0u, M, o));
        float v = ps * __expf(pm - M);
#pragma unroll
        for (int o = 16; o; o >>= 1) v += __shfl_xor_sync(~0u, v, o);
        if (tid == 0) lse_s = M + __logf(v);
    }
    __syncthreads();
    if (tid < NEMIT) {
        int b = row / TLEN;
        int col = (tid == 0) ? 0 : ys_pad[b * LMAX + tid - 1];
        int slot = g_slot[b * VOC + col];
        g_emit[(size_t)row * NEMIT + tid] = g_gath[(size_t)row * GSTRIDE + slot] - lse_s;
    }
}

// ---------------- kernel 3: CTC forward recursion ----------------------
__global__ __launch_bounds__(224) void ctc_kernel(const int* __restrict__ hlens,
                                                  const int* __restrict__ ys_pad,
                                                  const int* __restrict__ ys_lens) {
    const int b = blockIdx.x;
    const int s = threadIdx.x;
    __shared__ float al[2][SEXT + 2];

    const float* eb = g_emit + (size_t)b * TLEN * NEMIT;
    const bool act = s < SEXT;
    const int j = (s & 1) ? ((s >> 1) + 1) : 0;

    bool skip = false;
    if (act && (s & 1) && s >= 3) {
        int cur  = ys_pad[b * LMAX + (s >> 1)];
        int prev = ys_pad[b * LMAX + (s >> 1) - 1];
        skip = (cur != prev);
    }

    if (s < 2) { al[0][s] = NEGV; al[1][s] = NEGV; }
    if (act) al[0][s + 2] = (s < 2) ? eb[j] : NEGV;

    const int hl = hlens[b];
    float e1 = NEGV;
    if (act && hl > 1) e1 = eb[NEMIT + j];
    __syncthreads();

    int p = 0;
    for (int t = 1; t < hl; t++) {
        float e = e1;
        if (act && t + 1 < hl) e1 = eb[(size_t)(t + 1) * NEMIT + j];

        if (act) {
            float a0 = al[p][s + 2];
            float a1 = al[p][s + 1];
            float a2 = skip ? al[p][s] : NEGV;
            float m = fmaxf(a0, fmaxf(a1, a2));
            float w = __expf(a0 - m) + __expf(a1 - m) + __expf(a2 - m);
            al[1 - p][s + 2] = m + __logf(w) + e;
        }
        __syncthreads();
        p ^= 1;
    }

    if (s == 0) {
        int L = ys_lens[b];
        int idx = 2 * L;
        float aL = al[p][idx + 2];
        float aP = al[p][idx + 1];
        float m = fmaxf(aL, aP);
        float loss = -(m + __logf(__expf(aL - m) + __expf(aP - m)));
        if (!isfinite(loss) || loss >= 1e29f) loss = 0.f;
        g_loss[b] = loss;
    }
}

// ---------------- kernel 4: final reduce --------------------------------
__global__ void finalize_kernel(float* __restrict__ out) {
    float sum = 0.f;
    for (int i = 0; i < BATCH; i++) sum += g_loss[i];
    out[0] = sum / (float)BATCH;
}

// ---------------- launch --------------------------------------------------
extern "C" void kernel_launch(void* const* d_in, const int* in_sizes, int n_in,
                              void* d_out, int out_size) {
    const float* hs     = (const float*)d_in[0];
    const float* Wm     = (const float*)d_in[1];
    const float* bias   = (const float*)d_in[2];
    const int* hlens    = (const int*)d_in[3];
    const int* ys_pad   = (const int*)d_in[4];
    const int* ys_lens  = (const int*)d_in[5];
    float* out = (float*)d_out;

    cudaFuncSetAttribute(mma_gemm_kernel,
                         cudaFuncAttributeMaxDynamicSharedMemorySize, DYN_SMEM);

    init_slot_kernel<<<(BATCH * VOC + 255) / 256, 256>>>();
    write_slot_kernel<<<BATCH, 128>>>(ys_pad);
    convA_kernel<<<(NROWS * DDIM / 4 + 255) / 256, 256>>>(hs);
    transW_kernel<<<dim3(VPAD / 32, DDIM / 32), dim3(32, 8)>>>(Wm);

    dim3 gemm_grid(NTILES, NROWS / 128);  // (32, 100)
    mma_gemm_kernel<<<gemm_grid, 256, DYN_SMEM>>>(bias);

    emit_kernel<<<NROWS, 128>>>(ys_pad);
    ctc_kernel<<<BATCH, 224>>>(hlens, ys_pad, ys_lens);
    finalize_kernel<<<1, 1>>>(out);
}